// round 10
// baseline (speedup 1.0000x reference)
#include <cuda_runtime.h>
#include <cuda_bf16.h>
#include <math.h>
#include <cstdint>
#include <cstddef>

#define T_TOK 8192
#define D_IN  1024
#define DFF   4096
#define NE    8

// ---------------- device scratch (ONLY referenced inside kernels) -----------
__device__ int   g_count[NE];
__device__ int   g_slot[NE * T_TOK];
__device__ float g_scale[T_TOK];

__device__ __align__(16) __nv_bfloat16 g_x_hi[(size_t)T_TOK * D_IN];
__device__ __align__(16) __nv_bfloat16 g_x_lo[(size_t)T_TOK * D_IN];
__device__ __align__(16) __nv_bfloat16 g_h_hi[(size_t)T_TOK * DFF];      // token-indexed
__device__ __align__(16) __nv_bfloat16 g_h_lo[(size_t)T_TOK * DFF];
__device__ __align__(16) __nv_bfloat16 g_w1_hi[(size_t)NE * D_IN * DFF]; // [E][K][N] native
__device__ __align__(16) __nv_bfloat16 g_w1_lo[(size_t)NE * D_IN * DFF];
__device__ __align__(16) __nv_bfloat16 g_w2_hi[(size_t)NE * DFF * D_IN];
__device__ __align__(16) __nv_bfloat16 g_w2_lo[(size_t)NE * DFF * D_IN];

// ---------------- PTX helpers ----------------
__device__ __forceinline__ unsigned smem_u32(const void* p) {
    unsigned a;
    asm("{ .reg .u64 t; cvta.to.shared.u64 t, %1; cvt.u32.u64 %0, t; }" : "=r"(a) : "l"(p));
    return a;
}
#define LDSM_X4(r, a) \
    asm volatile("ldmatrix.sync.aligned.m8n8.x4.shared.b16 {%0,%1,%2,%3}, [%4];" \
        : "=r"((r)[0]), "=r"((r)[1]), "=r"((r)[2]), "=r"((r)[3]) : "r"(a))
#define LDSM_X4_T(r, a) \
    asm volatile("ldmatrix.sync.aligned.m8n8.x4.trans.shared.b16 {%0,%1,%2,%3}, [%4];" \
        : "=r"((r)[0]), "=r"((r)[1]), "=r"((r)[2]), "=r"((r)[3]) : "r"(a))
#define MMA_BF16(d, a, b0, b1) \
    asm volatile("mma.sync.aligned.m16n8k16.row.col.f32.bf16.bf16.f32 " \
        "{%0,%1,%2,%3}, {%4,%5,%6,%7}, {%8,%9}, {%0,%1,%2,%3};" \
        : "+f"((d)[0]), "+f"((d)[1]), "+f"((d)[2]), "+f"((d)[3]) \
        : "r"((a)[0]), "r"((a)[1]), "r"((a)[2]), "r"((a)[3]), "r"(b0), "r"(b1))

// ---------------- misc helpers ----------------
__device__ __forceinline__ float gelu_exact(float v) {
    return 0.5f * v * (1.0f + erff(v * 0.70710678118654752f));
}
__device__ __forceinline__ unsigned pack_bf2(float a, float b) {
    __nv_bfloat162 t = __floats2bfloat162_rn(a, b);
    return reinterpret_cast<unsigned&>(t);
}

// ---------------- kernel 0: zero counters ----------------
__global__ void zero_counts_k() { if (threadIdx.x < NE) g_count[threadIdx.x] = 0; }

// ---------------- kernel 1: router (proven) ----------------
__global__ void router_k(const float* __restrict__ x, const float* __restrict__ gw) {
    int warp = (blockIdx.x * blockDim.x + threadIdx.x) >> 5;
    int lane = threadIdx.x & 31;
    if (warp >= T_TOK) return;
    const float* xr = x + (size_t)warp * D_IN;
    double acc[NE];
#pragma unroll
    for (int j = 0; j < NE; j++) acc[j] = 0.0;
    for (int d = lane; d < D_IN; d += 32) {
        float xv = xr[d];
        const float4* g4 = reinterpret_cast<const float4*>(gw + d * NE);
        float4 a = g4[0], b = g4[1];
        acc[0] += (double)xv * a.x; acc[1] += (double)xv * a.y;
        acc[2] += (double)xv * a.z; acc[3] += (double)xv * a.w;
        acc[4] += (double)xv * b.x; acc[5] += (double)xv * b.y;
        acc[6] += (double)xv * b.z; acc[7] += (double)xv * b.w;
    }
#pragma unroll
    for (int j = 0; j < NE; j++)
#pragma unroll
        for (int s = 16; s > 0; s >>= 1)
            acc[j] += __shfl_xor_sync(0xffffffffu, acc[j], s);
    if (lane == 0) {
        double m = acc[0]; int am = 0;
#pragma unroll
        for (int j = 1; j < NE; j++) if (acc[j] > m) { m = acc[j]; am = j; }
        double s = 0.0;
#pragma unroll
        for (int j = 0; j < NE; j++) s += exp(acc[j] - m);
        g_scale[warp] = (float)(1.0 / s);
        int pos = atomicAdd(&g_count[am], 1);
        g_slot[am * T_TOK + pos] = warp;
    }
}

// ---------------- elementwise hi/lo split; targets selected IN-KERNEL -------
template <int SEL>   // 0: x planes, 1: w1 planes, 2: w2 planes
__global__ void split_sel_k(const float* __restrict__ in) {
    __nv_bfloat16* hi = (SEL == 0) ? g_x_hi : (SEL == 1) ? g_w1_hi : g_w2_hi;
    __nv_bfloat16* lo = (SEL == 0) ? g_x_lo : (SEL == 1) ? g_w1_lo : g_w2_lo;
    size_t i = (size_t)blockIdx.x * blockDim.x + threadIdx.x;
    float4 v = reinterpret_cast<const float4*>(in)[i];
    float f[4] = {v.x, v.y, v.z, v.w}, l[4];
#pragma unroll
    for (int q = 0; q < 4; q++) {
        float h = __bfloat162float(__float2bfloat16_rn(f[q]));
        l[q] = f[q] - h;
    }
    reinterpret_cast<uint2*>(hi)[i] = make_uint2(pack_bf2(f[0], f[1]), pack_bf2(f[2], f[3]));
    reinterpret_cast<uint2*>(lo)[i] = make_uint2(pack_bf2(l[0], l[1]), pack_bf2(l[2], l[3]));
}

// ---------------- grouped GEMM: raw mma, LDG+STS staging (R7-proven) --------
// Block 128x128, k-step 16, 8 warps (wm = wid&1, wn = wid>>1). R7 fragment math.
// smem: Ahi 4K | Alo 4K | Bhi 4K | Blo 4K (16 KB static), register prefetch.
// A swizzle: chunk c ^= (row>>2)&1.  B swizzle: n-chunk nc ^= krow&7.
// ALL plane pointers resolved from device globals INSIDE the kernel.
template <bool DO_GELU>
__global__ __launch_bounds__(256)
void moe_mma(const float* __restrict__ Bias, float* __restrict__ OutF,
             int K, int N) {
    const int e  = blockIdx.z;
    const int Me = g_count[e];
    const int m0 = blockIdx.y * 128;
    if (m0 >= Me) return;
    const int n0 = blockIdx.x * 128;

    const __nv_bfloat16* Ahi = DO_GELU ? g_x_hi : g_h_hi;
    const __nv_bfloat16* Alo = DO_GELU ? g_x_lo : g_h_lo;
    const __nv_bfloat16* Whi = DO_GELU ? g_w1_hi : g_w2_hi;
    const __nv_bfloat16* Wlo = DO_GELU ? g_w1_lo : g_w2_lo;

    __shared__ __align__(16) unsigned char sm[16384];
    __shared__ int toks[128];

    const int tid = threadIdx.x;
    if (tid < 128) {
        int p = m0 + tid;
        toks[tid] = (p < Me) ? g_slot[e * T_TOK + p] : -1;
    }
    __syncthreads();

    // A staging: thread -> (row ar, 16B chunk ac8 of the 32B row)
    const int ar  = tid >> 1;
    const int ac8 = tid & 1;
    const int tokA = toks[ar];
    const __nv_bfloat16* aph = (tokA >= 0) ? (Ahi + (size_t)tokA * K + ac8 * 8) : nullptr;
    const __nv_bfloat16* apl = (tokA >= 0) ? (Alo + (size_t)tokA * K + ac8 * 8) : nullptr;
    const unsigned aoff = (unsigned)(ar * 32 + ((ac8 ^ ((ar >> 2) & 1)) << 4));
    // B staging: thread -> (k-row bk, n-chunk bnc)
    const int bk  = tid >> 4;
    const int bnc = tid & 15;
    const size_t bbase = ((size_t)e * K + bk) * N + n0 + bnc * 8;
    const unsigned boff = (unsigned)(bk * 256 + ((bnc ^ (bk & 7)) << 4));

    const int wid = tid >> 5, lane = tid & 31;
    const int wm = wid & 1, wn = wid >> 1;
    const int lane4 = lane & 15, laneh = lane >> 4;
    const unsigned offA = (unsigned)((wm * 64 + lane4) * 32 + ((laneh ^ ((lane4 >> 2) & 1)) << 4));
    const int khalf = (lane >> 4) & 1, ngrp = (lane >> 3) & 1, tt = lane & 7;
    const int krow = khalf * 8 + tt;
    const unsigned offB0 = (unsigned)(8192 + krow * 256 + (((wn * 4 + ngrp)     ^ (krow & 7)) << 4));
    const unsigned offB1 = (unsigned)(8192 + krow * 256 + (((wn * 4 + 2 + ngrp) ^ (krow & 7)) << 4));
    const unsigned base = smem_u32(sm);

    float acc[4][4][4];
#pragma unroll
    for (int i = 0; i < 4; i++)
#pragma unroll
        for (int j = 0; j < 4; j++)
#pragma unroll
            for (int q = 0; q < 4; q++) acc[i][j][q] = 0.0f;

    // prefetch k0 = 0 into registers (proven pattern)
    uint4 pah = make_uint4(0u, 0u, 0u, 0u), pal = pah;
    if (aph) {
        pah = *reinterpret_cast<const uint4*>(aph);
        pal = *reinterpret_cast<const uint4*>(apl);
    }
    uint4 pbh = *reinterpret_cast<const uint4*>(Whi + bbase);
    uint4 pbl = *reinterpret_cast<const uint4*>(Wlo + bbase);

    for (int k0 = 0; k0 < K; k0 += 16) {
        *reinterpret_cast<uint4*>(sm + aoff)          = pah;
        *reinterpret_cast<uint4*>(sm + 4096  + aoff)  = pal;
        *reinterpret_cast<uint4*>(sm + 8192  + boff)  = pbh;
        *reinterpret_cast<uint4*>(sm + 12288 + boff)  = pbl;
        __syncthreads();

        const int k1 = k0 + 16;
        if (k1 < K) {
            if (aph) {
                pah = *reinterpret_cast<const uint4*>(aph + k1);
                pal = *reinterpret_cast<const uint4*>(apl + k1);
            }
            pbh = *reinterpret_cast<const uint4*>(Whi + bbase + (size_t)k1 * N);
            pbl = *reinterpret_cast<const uint4*>(Wlo + bbase + (size_t)k1 * N);
        }

        unsigned ah[4][4], al[4][4], bh[2][4], bl[2][4];
#pragma unroll
        for (int mi = 0; mi < 4; mi++) {
            LDSM_X4(ah[mi], base + offA + mi * 512);
            LDSM_X4(al[mi], base + 4096 + offA + mi * 512);
        }
        LDSM_X4_T(bh[0], base + offB0);
        LDSM_X4_T(bh[1], base + offB1);
        LDSM_X4_T(bl[0], base + offB0 + 4096);
        LDSM_X4_T(bl[1], base + offB1 + 4096);

#pragma unroll
        for (int mi = 0; mi < 4; mi++)
#pragma unroll
            for (int nt = 0; nt < 4; nt++) {
                const int nj = nt >> 1, sel = nt & 1;
                MMA_BF16(acc[mi][nt], ah[mi], bh[nj][sel], bh[nj][sel + 2]);
                MMA_BF16(acc[mi][nt], ah[mi], bl[nj][sel], bl[nj][sel + 2]);
                MMA_BF16(acc[mi][nt], al[mi], bh[nj][sel], bh[nj][sel + 2]);
            }
        __syncthreads();
    }

    // ---------------- epilogue (R7 mapping) ----------------
    // acc[mi][nt]: d0=(r0,c), d1=(r0,c+1), d2=(r0+8,c), d3=(r0+8,c+1)
    float bb[4][2];
#pragma unroll
    for (int nt = 0; nt < 4; nt++) {
        const float2 bv = *reinterpret_cast<const float2*>(
            Bias + (size_t)e * N + n0 + wn * 32 + nt * 8 + (lane & 3) * 2);
        bb[nt][0] = bv.x; bb[nt][1] = bv.y;
    }

#pragma unroll
    for (int mi = 0; mi < 4; mi++) {
        const int r0 = wm * 64 + mi * 16 + (lane >> 2);
        const int t0 = toks[r0], t1 = toks[r0 + 8];
        if (DO_GELU) {
#pragma unroll
            for (int nt = 0; nt < 4; nt++) {
                const int col = n0 + wn * 32 + nt * 8 + (lane & 3) * 2;
                if (t0 >= 0) {
                    float v0 = gelu_exact(acc[mi][nt][0] + bb[nt][0]);
                    float v1 = gelu_exact(acc[mi][nt][1] + bb[nt][1]);
                    float h0 = __bfloat162float(__float2bfloat16_rn(v0));
                    float h1 = __bfloat162float(__float2bfloat16_rn(v1));
                    *reinterpret_cast<unsigned*>(g_h_hi + (size_t)t0 * N + col) = pack_bf2(v0, v1);
                    *reinterpret_cast<unsigned*>(g_h_lo + (size_t)t0 * N + col) = pack_bf2(v0 - h0, v1 - h1);
                }
                if (t1 >= 0) {
                    float v2 = gelu_exact(acc[mi][nt][2] + bb[nt][0]);
                    float v3 = gelu_exact(acc[mi][nt][3] + bb[nt][1]);
                    float h2 = __bfloat162float(__float2bfloat16_rn(v2));
                    float h3 = __bfloat162float(__float2bfloat16_rn(v3));
                    *reinterpret_cast<unsigned*>(g_h_hi + (size_t)t1 * N + col) = pack_bf2(v2, v3);
                    *reinterpret_cast<unsigned*>(g_h_lo + (size_t)t1 * N + col) = pack_bf2(v2 - h2, v3 - h3);
                }
            }
        } else {
            const float s0 = (t0 >= 0) ? g_scale[t0] : 0.0f;
            const float s1 = (t1 >= 0) ? g_scale[t1] : 0.0f;
#pragma unroll
            for (int nt = 0; nt < 4; nt++) {
                const int col = n0 + wn * 32 + nt * 8 + (lane & 3) * 2;
                if (t0 >= 0) {
                    float2 v = make_float2((acc[mi][nt][0] + bb[nt][0]) * s0,
                                           (acc[mi][nt][1] + bb[nt][1]) * s0);
                    *reinterpret_cast<float2*>(OutF + (size_t)t0 * N + col) = v;
                }
                if (t1 >= 0) {
                    float2 v = make_float2((acc[mi][nt][2] + bb[nt][0]) * s1,
                                           (acc[mi][nt][3] + bb[nt][1]) * s1);
                    *reinterpret_cast<float2*>(OutF + (size_t)t1 * N + col) = v;
                }
            }
        }
    }
}

// ---------------- launch ----------------
extern "C" void kernel_launch(void* const* d_in, const int* in_sizes, int n_in,
                              void* d_out, int out_size) {
    const float* x  = (const float*)d_in[0];
    const float* gw = (const float*)d_in[1];
    const float* w1 = (const float*)d_in[2];
    const float* b1 = (const float*)d_in[3];
    const float* w2 = (const float*)d_in[4];
    const float* b2 = (const float*)d_in[5];
    float* out = (float*)d_out;

    zero_counts_k<<<1, 32>>>();
    router_k<<<(T_TOK * 32) / 256, 256>>>(x, gw);

    split_sel_k<0><<<((size_t)T_TOK * D_IN / 4) / 256, 256>>>(x);
    split_sel_k<1><<<((size_t)NE * D_IN * DFF / 4) / 256, 256>>>(w1);
    split_sel_k<2><<<((size_t)NE * DFF * D_IN / 4) / 256, 256>>>(w2);

    dim3 g1(DFF / 128, T_TOK / 128, NE);   // empty m-tiles early-exit
    moe_mma<true><<<g1, 256>>>(b1, nullptr, D_IN, DFF);

    dim3 g2(D_IN / 128, T_TOK / 128, NE);
    moe_mma<false><<<g2, 256>>>(b2, out, DFF, D_IN);
}

// round 11
// speedup vs baseline: 1.2197x; 1.2197x over previous
#include <cuda_runtime.h>
#include <cuda_bf16.h>
#include <math.h>
#include <cstdint>
#include <cstddef>

#define T_TOK 8192
#define D_IN  1024
#define DFF   4096
#define NE    8

// ---------------- device scratch (ONLY referenced inside kernels) -----------
__device__ int   g_count[NE];
__device__ int   g_slot[NE * T_TOK];
__device__ float g_scale[T_TOK];

__device__ __align__(16) __nv_bfloat16 g_x_hi[(size_t)T_TOK * D_IN];
__device__ __align__(16) __nv_bfloat16 g_x_lo[(size_t)T_TOK * D_IN];
__device__ __align__(16) __nv_bfloat16 g_h_hi[(size_t)T_TOK * DFF];      // token-indexed
__device__ __align__(16) __nv_bfloat16 g_h_lo[(size_t)T_TOK * DFF];
__device__ __align__(16) __nv_bfloat16 g_w1_hi[(size_t)NE * D_IN * DFF]; // [E][K][N] native
__device__ __align__(16) __nv_bfloat16 g_w1_lo[(size_t)NE * D_IN * DFF];
__device__ __align__(16) __nv_bfloat16 g_w2_hi[(size_t)NE * DFF * D_IN];
__device__ __align__(16) __nv_bfloat16 g_w2_lo[(size_t)NE * DFF * D_IN];

// ---------------- PTX helpers ----------------
__device__ __forceinline__ unsigned smem_u32(const void* p) {
    unsigned a;
    asm("{ .reg .u64 t; cvta.to.shared.u64 t, %1; cvt.u32.u64 %0, t; }" : "=r"(a) : "l"(p));
    return a;
}
#define LDSM_X4(r, a) \
    asm volatile("ldmatrix.sync.aligned.m8n8.x4.shared.b16 {%0,%1,%2,%3}, [%4];" \
        : "=r"((r)[0]), "=r"((r)[1]), "=r"((r)[2]), "=r"((r)[3]) : "r"(a))
#define LDSM_X4_T(r, a) \
    asm volatile("ldmatrix.sync.aligned.m8n8.x4.trans.shared.b16 {%0,%1,%2,%3}, [%4];" \
        : "=r"((r)[0]), "=r"((r)[1]), "=r"((r)[2]), "=r"((r)[3]) : "r"(a))
#define MMA_BF16(d, a, b0, b1) \
    asm volatile("mma.sync.aligned.m16n8k16.row.col.f32.bf16.bf16.f32 " \
        "{%0,%1,%2,%3}, {%4,%5,%6,%7}, {%8,%9}, {%0,%1,%2,%3};" \
        : "+f"((d)[0]), "+f"((d)[1]), "+f"((d)[2]), "+f"((d)[3]) \
        : "r"((a)[0]), "r"((a)[1]), "r"((a)[2]), "r"((a)[3]), "r"(b0), "r"(b1))

// ---------------- misc helpers ----------------
__device__ __forceinline__ float gelu_exact(float v) {
    return 0.5f * v * (1.0f + erff(v * 0.70710678118654752f));
}
__device__ __forceinline__ unsigned pack_bf2(float a, float b) {
    __nv_bfloat162 t = __floats2bfloat162_rn(a, b);
    return reinterpret_cast<unsigned&>(t);
}

// ---------------- kernel 0: zero counters ----------------
__global__ void zero_counts_k() { if (threadIdx.x < NE) g_count[threadIdx.x] = 0; }

// ---------------- kernel 1: router (proven) ----------------
__global__ void router_k(const float* __restrict__ x, const float* __restrict__ gw) {
    int warp = (blockIdx.x * blockDim.x + threadIdx.x) >> 5;
    int lane = threadIdx.x & 31;
    if (warp >= T_TOK) return;
    const float* xr = x + (size_t)warp * D_IN;
    double acc[NE];
#pragma unroll
    for (int j = 0; j < NE; j++) acc[j] = 0.0;
    for (int d = lane; d < D_IN; d += 32) {
        float xv = xr[d];
        const float4* g4 = reinterpret_cast<const float4*>(gw + d * NE);
        float4 a = g4[0], b = g4[1];
        acc[0] += (double)xv * a.x; acc[1] += (double)xv * a.y;
        acc[2] += (double)xv * a.z; acc[3] += (double)xv * a.w;
        acc[4] += (double)xv * b.x; acc[5] += (double)xv * b.y;
        acc[6] += (double)xv * b.z; acc[7] += (double)xv * b.w;
    }
#pragma unroll
    for (int j = 0; j < NE; j++)
#pragma unroll
        for (int s = 16; s > 0; s >>= 1)
            acc[j] += __shfl_xor_sync(0xffffffffu, acc[j], s);
    if (lane == 0) {
        double m = acc[0]; int am = 0;
#pragma unroll
        for (int j = 1; j < NE; j++) if (acc[j] > m) { m = acc[j]; am = j; }
        double s = 0.0;
#pragma unroll
        for (int j = 0; j < NE; j++) s += exp(acc[j] - m);
        g_scale[warp] = (float)(1.0 / s);
        int pos = atomicAdd(&g_count[am], 1);
        g_slot[am * T_TOK + pos] = warp;
    }
}

// ---------------- elementwise hi/lo split; targets selected IN-KERNEL -------
template <int SEL>   // 0: x planes, 1: w1 planes, 2: w2 planes
__global__ void split_sel_k(const float* __restrict__ in) {
    __nv_bfloat16* hi = (SEL == 0) ? g_x_hi : (SEL == 1) ? g_w1_hi : g_w2_hi;
    __nv_bfloat16* lo = (SEL == 0) ? g_x_lo : (SEL == 1) ? g_w1_lo : g_w2_lo;
    size_t i = (size_t)blockIdx.x * blockDim.x + threadIdx.x;
    float4 v = reinterpret_cast<const float4*>(in)[i];
    float f[4] = {v.x, v.y, v.z, v.w}, l[4];
#pragma unroll
    for (int q = 0; q < 4; q++) {
        float h = __bfloat162float(__float2bfloat16_rn(f[q]));
        l[q] = f[q] - h;
    }
    reinterpret_cast<uint2*>(hi)[i] = make_uint2(pack_bf2(f[0], f[1]), pack_bf2(f[2], f[3]));
    reinterpret_cast<uint2*>(lo)[i] = make_uint2(pack_bf2(l[0], l[1]), pack_bf2(l[2], l[3]));
}

// ---------------- grouped GEMM: raw mma, double-buffered smem ---------------
// Block 128x128, k-step 16, 8 warps (wm = wid&1, wn = wid>>1). R7 fragment math.
// Two 16 KB stages: Ahi 4K | Alo 4K | Bhi 4K | Blo 4K each. ONE sync per k-step;
// STS to stage s^1 overlaps MMA on stage s. LDG register prefetch as proven.
// A swizzle: chunk c ^= (row>>2)&1.  B swizzle: n-chunk nc ^= krow&7.
template <bool DO_GELU>
__global__ __launch_bounds__(256, 2)
void moe_mma(const float* __restrict__ Bias, float* __restrict__ OutF,
             int K, int N) {
    const int e  = blockIdx.z;
    const int Me = g_count[e];
    const int m0 = blockIdx.y * 128;
    if (m0 >= Me) return;
    const int n0 = blockIdx.x * 128;

    const __nv_bfloat16* Ahi = DO_GELU ? g_x_hi : g_h_hi;
    const __nv_bfloat16* Alo = DO_GELU ? g_x_lo : g_h_lo;
    const __nv_bfloat16* Whi = DO_GELU ? g_w1_hi : g_w2_hi;
    const __nv_bfloat16* Wlo = DO_GELU ? g_w1_lo : g_w2_lo;

    __shared__ __align__(16) unsigned char sm[2][16384];
    __shared__ int toks[128];

    const int tid = threadIdx.x;
    if (tid < 128) {
        int p = m0 + tid;
        toks[tid] = (p < Me) ? g_slot[e * T_TOK + p] : -1;
    }
    __syncthreads();

    // A staging: thread -> (row ar, 16B chunk ac8 of the 32B row)
    const int ar  = tid >> 1;
    const int ac8 = tid & 1;
    const int tokA = toks[ar];
    const __nv_bfloat16* aph = (tokA >= 0) ? (Ahi + (size_t)tokA * K + ac8 * 8) : nullptr;
    const __nv_bfloat16* apl = (tokA >= 0) ? (Alo + (size_t)tokA * K + ac8 * 8) : nullptr;
    const unsigned aoff = (unsigned)(ar * 32 + ((ac8 ^ ((ar >> 2) & 1)) << 4));
    // B staging: thread -> (k-row bk, n-chunk bnc)
    const int bk  = tid >> 4;
    const int bnc = tid & 15;
    const size_t bbase = ((size_t)e * K + bk) * N + n0 + bnc * 8;
    const unsigned boff = (unsigned)(bk * 256 + ((bnc ^ (bk & 7)) << 4));

    const int wid = tid >> 5, lane = tid & 31;
    const int wm = wid & 1, wn = wid >> 1;
    const int lane4 = lane & 15, laneh = lane >> 4;
    const unsigned offA = (unsigned)((wm * 64 + lane4) * 32 + ((laneh ^ ((lane4 >> 2) & 1)) << 4));
    const int khalf = (lane >> 4) & 1, ngrp = (lane >> 3) & 1, tt = lane & 7;
    const int krow = khalf * 8 + tt;
    const unsigned offB0 = (unsigned)(8192 + krow * 256 + (((wn * 4 + ngrp)     ^ (krow & 7)) << 4));
    const unsigned offB1 = (unsigned)(8192 + krow * 256 + (((wn * 4 + 2 + ngrp) ^ (krow & 7)) << 4));
    const unsigned base = smem_u32(sm);

    float acc[4][4][4];
#pragma unroll
    for (int i = 0; i < 4; i++)
#pragma unroll
        for (int j = 0; j < 4; j++)
#pragma unroll
            for (int q = 0; q < 4; q++) acc[i][j][q] = 0.0f;

    // prologue: k0 regs -> stage 0 -> sync
    uint4 pah = make_uint4(0u, 0u, 0u, 0u), pal = pah;
    if (aph) {
        pah = *reinterpret_cast<const uint4*>(aph);
        pal = *reinterpret_cast<const uint4*>(apl);
    }
    uint4 pbh = *reinterpret_cast<const uint4*>(Whi + bbase);
    uint4 pbl = *reinterpret_cast<const uint4*>(Wlo + bbase);
    {
        unsigned char* s0 = (unsigned char*)sm;
        *reinterpret_cast<uint4*>(s0 + aoff)          = pah;
        *reinterpret_cast<uint4*>(s0 + 4096  + aoff)  = pal;
        *reinterpret_cast<uint4*>(s0 + 8192  + boff)  = pbh;
        *reinterpret_cast<uint4*>(s0 + 12288 + boff)  = pbl;
    }
    __syncthreads();

    const int KS = K / 16;
    for (int i = 0; i < KS; i++) {
        const int k1 = (i + 1) * 16;
        // issue next-stage LDGs early (land while MMA runs)
        if (k1 < K) {
            if (aph) {
                pah = *reinterpret_cast<const uint4*>(aph + k1);
                pal = *reinterpret_cast<const uint4*>(apl + k1);
            }
            pbh = *reinterpret_cast<const uint4*>(Whi + bbase + (size_t)k1 * N);
            pbl = *reinterpret_cast<const uint4*>(Wlo + bbase + (size_t)k1 * N);
        }

        const unsigned sb = base + (i & 1) * 16384;
        unsigned ah[4][4], al[4][4], bh[2][4], bl[2][4];
#pragma unroll
        for (int mi = 0; mi < 4; mi++) {
            LDSM_X4(ah[mi], sb + offA + mi * 512);
            LDSM_X4(al[mi], sb + 4096 + offA + mi * 512);
        }
        LDSM_X4_T(bh[0], sb + offB0);
        LDSM_X4_T(bh[1], sb + offB1);
        LDSM_X4_T(bl[0], sb + offB0 + 4096);
        LDSM_X4_T(bl[1], sb + offB1 + 4096);

#pragma unroll
        for (int mi = 0; mi < 4; mi++)
#pragma unroll
            for (int nt = 0; nt < 4; nt++) {
                const int nj = nt >> 1, sel = nt & 1;
                MMA_BF16(acc[mi][nt], ah[mi], bh[nj][sel], bh[nj][sel + 2]);
                MMA_BF16(acc[mi][nt], ah[mi], bl[nj][sel], bl[nj][sel + 2]);
                MMA_BF16(acc[mi][nt], al[mi], bh[nj][sel], bh[nj][sel + 2]);
            }

        // store next stage (other buffer — no hazard with this stage's LDSMs)
        if (k1 < K) {
            unsigned char* sn = (unsigned char*)sm + ((i + 1) & 1) * 16384;
            *reinterpret_cast<uint4*>(sn + aoff)          = pah;
            *reinterpret_cast<uint4*>(sn + 4096  + aoff)  = pal;
            *reinterpret_cast<uint4*>(sn + 8192  + boff)  = pbh;
            *reinterpret_cast<uint4*>(sn + 12288 + boff)  = pbl;
        }
        __syncthreads();
    }

    // ---------------- epilogue (R7 mapping) ----------------
    // acc[mi][nt]: d0=(r0,c), d1=(r0,c+1), d2=(r0+8,c), d3=(r0+8,c+1)
    float bb[4][2];
#pragma unroll
    for (int nt = 0; nt < 4; nt++) {
        const float2 bv = *reinterpret_cast<const float2*>(
            Bias + (size_t)e * N + n0 + wn * 32 + nt * 8 + (lane & 3) * 2);
        bb[nt][0] = bv.x; bb[nt][1] = bv.y;
    }

#pragma unroll
    for (int mi = 0; mi < 4; mi++) {
        const int r0 = wm * 64 + mi * 16 + (lane >> 2);
        const int t0 = toks[r0], t1 = toks[r0 + 8];
        if (DO_GELU) {
#pragma unroll
            for (int nt = 0; nt < 4; nt++) {
                const int col = n0 + wn * 32 + nt * 8 + (lane & 3) * 2;
                if (t0 >= 0) {
                    float v0 = gelu_exact(acc[mi][nt][0] + bb[nt][0]);
                    float v1 = gelu_exact(acc[mi][nt][1] + bb[nt][1]);
                    float h0 = __bfloat162float(__float2bfloat16_rn(v0));
                    float h1 = __bfloat162float(__float2bfloat16_rn(v1));
                    *reinterpret_cast<unsigned*>(g_h_hi + (size_t)t0 * N + col) = pack_bf2(v0, v1);
                    *reinterpret_cast<unsigned*>(g_h_lo + (size_t)t0 * N + col) = pack_bf2(v0 - h0, v1 - h1);
                }
                if (t1 >= 0) {
                    float v2 = gelu_exact(acc[mi][nt][2] + bb[nt][0]);
                    float v3 = gelu_exact(acc[mi][nt][3] + bb[nt][1]);
                    float h2 = __bfloat162float(__float2bfloat16_rn(v2));
                    float h3 = __bfloat162float(__float2bfloat16_rn(v3));
                    *reinterpret_cast<unsigned*>(g_h_hi + (size_t)t1 * N + col) = pack_bf2(v2, v3);
                    *reinterpret_cast<unsigned*>(g_h_lo + (size_t)t1 * N + col) = pack_bf2(v2 - h2, v3 - h3);
                }
            }
        } else {
            const float s0 = (t0 >= 0) ? g_scale[t0] : 0.0f;
            const float s1 = (t1 >= 0) ? g_scale[t1] : 0.0f;
#pragma unroll
            for (int nt = 0; nt < 4; nt++) {
                const int col = n0 + wn * 32 + nt * 8 + (lane & 3) * 2;
                if (t0 >= 0) {
                    float2 v = make_float2((acc[mi][nt][0] + bb[nt][0]) * s0,
                                           (acc[mi][nt][1] + bb[nt][1]) * s0);
                    *reinterpret_cast<float2*>(OutF + (size_t)t0 * N + col) = v;
                }
                if (t1 >= 0) {
                    float2 v = make_float2((acc[mi][nt][2] + bb[nt][0]) * s1,
                                           (acc[mi][nt][3] + bb[nt][1]) * s1);
                    *reinterpret_cast<float2*>(OutF + (size_t)t1 * N + col) = v;
                }
            }
        }
    }
}

// ---------------- launch ----------------
extern "C" void kernel_launch(void* const* d_in, const int* in_sizes, int n_in,
                              void* d_out, int out_size) {
    const float* x  = (const float*)d_in[0];
    const float* gw = (const float*)d_in[1];
    const float* w1 = (const float*)d_in[2];
    const float* b1 = (const float*)d_in[3];
    const float* w2 = (const float*)d_in[4];
    const float* b2 = (const float*)d_in[5];
    float* out = (float*)d_out;

    zero_counts_k<<<1, 32>>>();
    router_k<<<(T_TOK * 32) / 256, 256>>>(x, gw);

    split_sel_k<0><<<((size_t)T_TOK * D_IN / 4) / 256, 256>>>(x);
    split_sel_k<1><<<((size_t)NE * D_IN * DFF / 4) / 256, 256>>>(w1);
    split_sel_k<2><<<((size_t)NE * DFF * D_IN / 4) / 256, 256>>>(w2);

    dim3 g1(DFF / 128, T_TOK / 128, NE);   // empty m-tiles early-exit
    moe_mma<true><<<g1, 256>>>(b1, nullptr, D_IN, DFF);

    dim3 g2(D_IN / 128, T_TOK / 128, NE);
    moe_mma<false><<<g2, 256>>>(b2, out, DFF, D_IN);
}